// round 5
// baseline (speedup 1.0000x reference)
#include <cuda_runtime.h>
#include <cuda_bf16.h>
#include <cstdint>

// Problem constants
#define BB        2048
#define TT        256
#define LDIM      32
#define NTH       256
#define CTA_ROWS  16              // 8 warps x 2 rows
#define NCTA      (BB / CTA_ROWS) // 128

// ---------------------------------------------------------------------------
// Shared memory. Weight blocks are re-packed so one lane-owned float4 covers
// a 2k x 2j (or 2k x 4j for Whh) tile usable for BOTH rows of the warp.
// All activation reads are warp-broadcast float4 (single address -> 1 wavefront).
// Scratch regions are warp-private: only __syncwarp() needed in the loop.
// ---------------------------------------------------------------------------
struct Smem {
    float WxiQ[32 * 32 * 4];  // [kp][lane][4]: {W[2l][2kp],W[2l+1][2kp],W[2l][2kp+1],W[2l+1][2kp+1]}
    float Wl3Q[10 * 32 * 4];  // same packing, K=20
    float WhhQ[16 * 32 * 8];  // [kp][lane][8]: j=4l+(c&3), k=2kp+(c>>2)
    float WxiA[3 * 64];       // one-hot columns of W_xi: [a][j]
    float bxi[64];
    float Wl1[20 * 64];       // row-major
    float Wl2[20 * 20];       // row-major
    float bl1v[24];
    float bl2v[24];
    float bl3v[64];
    float h[CTA_ROWS][32];
    float c[CTA_ROWS][32];
    float zp[CTA_ROWS][64];
    float z1[CTA_ROWS][20];   // row base = r*80B -> 16B aligned
    float z2[CTA_ROWS][20];
    float gate[CTA_ROWS][128];
    float ob[CTA_ROWS][8];
};

__device__ __forceinline__ float sigf(float x) {
    return __fdividef(1.0f, 1.0f + __expf(-x));
}
__device__ __forceinline__ float tanh_f(float x) {
    return 2.0f * sigf(2.0f * x) - 1.0f;   // rel err ~1e-6
}

__global__ __launch_bounds__(NTH, 1)
void ppo_rnn_kernel(const float* __restrict__ obs,
                    const float* __restrict__ h0,
                    const float* __restrict__ c0,
                    const float* __restrict__ W1,
                    const float* __restrict__ b1,
                    const float* __restrict__ W_ih,
                    const float* __restrict__ W_hh,
                    const float* __restrict__ b_ih,
                    const float* __restrict__ b_hh,
                    const float* __restrict__ W_xi,
                    const float* __restrict__ b_xi,
                    const float* __restrict__ Wl1,
                    const float* __restrict__ bl1,
                    const float* __restrict__ Wl2,
                    const float* __restrict__ bl2,
                    const float* __restrict__ Wl3,
                    const float* __restrict__ bl3,
                    float* __restrict__ out)
{
    extern __shared__ float smraw[];
    Smem* s = reinterpret_cast<Smem*>(smraw);

    const int tid = threadIdx.x;
    const int l   = tid & 31;         // lane
    const int w   = tid >> 5;         // warp 0..7
    const int r0  = 2 * w, r1 = 2 * w + 1;   // CTA-local rows
    const int b0  = blockIdx.x * CTA_ROWS;
    const int g0  = b0 + r0, g1 = b0 + r1;   // global rows

    // ---------------- prologue: pack weights into smem -------------------
    for (int i = tid; i < 32 * 32 * 4; i += NTH) {
        int kp = i >> 7, rem = i & 127;
        int ll = rem >> 2, cc = rem & 3;
        int j = 2 * ll + (cc & 1), k = 2 * kp + (cc >> 1);
        s->WxiQ[i] = W_xi[j * 67 + k];
    }
    for (int i = tid; i < 10 * 32 * 4; i += NTH) {
        int kp = i >> 7, rem = i & 127;
        int ll = rem >> 2, cc = rem & 3;
        int j = 2 * ll + (cc & 1), k = 2 * kp + (cc >> 1);
        s->Wl3Q[i] = Wl3[j * 20 + k];
    }
    for (int i = tid; i < 16 * 32 * 8; i += NTH) {
        int kp = i >> 8, rem = i & 255;
        int ll = rem >> 3, cc = rem & 7;
        int j = 4 * ll + (cc & 3), k = 2 * kp + (cc >> 2);
        s->WhhQ[i] = W_hh[j * 32 + k];
    }
    for (int i = tid; i < 3 * 64; i += NTH) {
        int a = i >> 6, j = i & 63;
        s->WxiA[i] = W_xi[j * 67 + 64 + a];
    }
    for (int i = tid; i < 64; i += NTH) { s->bxi[i] = b_xi[i]; s->bl3v[i] = bl3[i]; }
    for (int i = tid; i < 20 * 64; i += NTH) s->Wl1[i] = Wl1[i];
    for (int i = tid; i < 20 * 20; i += NTH) s->Wl2[i] = Wl2[i];
    for (int i = tid; i < 20; i += NTH) { s->bl1v[i] = bl1[i]; s->bl2v[i] = bl2[i]; }
    for (int i = tid; i < CTA_ROWS * 32; i += NTH) {
        int r = i >> 5, kk = i & 31;
        s->h[r][kk] = h0[(b0 + r) * 32 + kk];
        s->c[r][kk] = c0[(b0 + r) * 32 + kk];
    }

    // Fold M = W_ih @ W1 (my 4 gate cols), bvec = W_ih@b1 + b_ih + b_hh.
    float M[4][4], bv[4];
    {
        const int j0 = 4 * l;
        #pragma unroll
        for (int jj = 0; jj < 4; ++jj) {
            const int j = j0 + jj;
            float a0 = 0.f, m0 = 0.f, m1 = 0.f, m2 = 0.f, m3 = 0.f;
            for (int m = 0; m < 64; ++m) {
                float wv = W_ih[j * 64 + m];
                a0 += wv * b1[m];
                m0 += wv * W1[m * 4 + 0];
                m1 += wv * W1[m * 4 + 1];
                m2 += wv * W1[m * 4 + 2];
                m3 += wv * W1[m * 4 + 3];
            }
            bv[jj] = a0 + b_ih[j] + b_hh[j];
            M[jj][0] = m0; M[jj][1] = m1; M[jj][2] = m2; M[jj][3] = m3;
        }
    }
    __syncthreads();   // the ONLY CTA-wide barrier

    // obs prefetch: one field per loader lane, one step ahead
    const bool loader = (l < 7) || (l >= 16 && l < 23);
    const int  lfld   = (l < 16) ? l : (l - 16);
    const int  lrcta  = (l < 16) ? r0 : r1;
    const float* obp  = obs + (size_t)((l < 16) ? g0 : g1) * TT * 7 + lfld;
    float obreg = loader ? obp[0] : 0.f;

    // ---------------- sequential scan over T -----------------------------
    for (int t = 0; t < TT; ++t) {
        if (loader) s->ob[lrcta][lfld] = obreg;
        __syncwarp();
        if (loader && t + 1 < TT) obreg = obp[(size_t)(t + 1) * 7];

        float4 obv0 = *(const float4*)&s->ob[r0][0];
        float4 obv1 = *(const float4*)&s->ob[r1][0];
        float ts00 = s->ob[r0][4], ts01 = s->ob[r0][5];
        float ts10 = s->ob[r1][4], ts11 = s->ob[r1][5];
        int  act0 = (int)s->ob[r0][6], act1 = (int)s->ob[r1][6];
        bool cond0 = (ts00 + ts01) != 0.f; float dt0 = ts01 - ts00;
        bool cond1 = (ts10 + ts11) != 0.f; float dt1 = ts11 - ts10;

        // S1: zp = [h;c] @ Wxi^T + bxi + onehot col  (lane owns cols 2l,2l+1; both rows)
        float a00, a01, a10, a11;
        {
            float2 bx = *(const float2*)&s->bxi[2 * l];
            float2 e0 = *(const float2*)&s->WxiA[act0 * 64 + 2 * l];
            float2 e1 = *(const float2*)&s->WxiA[act1 * 64 + 2 * l];
            a00 = bx.x + e0.x; a01 = bx.y + e0.y;
            a10 = bx.x + e1.x; a11 = bx.y + e1.y;
            #pragma unroll
            for (int g = 0; g < 16; ++g) {
                float4 v0 = (g < 8) ? *(const float4*)&s->h[r0][4 * g]
                                    : *(const float4*)&s->c[r0][4 * (g - 8)];
                float4 v1 = (g < 8) ? *(const float4*)&s->h[r1][4 * g]
                                    : *(const float4*)&s->c[r1][4 * (g - 8)];
                float4 wA = *(const float4*)&s->WxiQ[(2 * g) * 128 + 4 * l];
                float4 wB = *(const float4*)&s->WxiQ[(2 * g + 1) * 128 + 4 * l];
                a00 += v0.x * wA.x + v0.y * wA.z + v0.z * wB.x + v0.w * wB.z;
                a01 += v0.x * wA.y + v0.y * wA.w + v0.z * wB.y + v0.w * wB.w;
                a10 += v1.x * wA.x + v1.y * wA.z + v1.z * wB.x + v1.w * wB.z;
                a11 += v1.x * wA.y + v1.y * wA.w + v1.z * wB.y + v1.w * wB.w;
            }
            *(float2*)&s->zp[r0][2 * l] = make_float2(a00, a01);
            *(float2*)&s->zp[r1][2 * l] = make_float2(a10, a11);
        }
        __syncwarp();

        // S2: z1 = relu(zp @ Wl1^T + bl1)   lane j = l < 20, both rows
        if (l < 20) {
            float bb = s->bl1v[l];
            float s0 = bb, s1v = bb;
            #pragma unroll
            for (int g = 0; g < 16; ++g) {
                float4 wv = *(const float4*)&s->Wl1[l * 64 + 4 * g];
                float4 p0 = *(const float4*)&s->zp[r0][4 * g];
                float4 p1 = *(const float4*)&s->zp[r1][4 * g];
                s0  += p0.x * wv.x + p0.y * wv.y + p0.z * wv.z + p0.w * wv.w;
                s1v += p1.x * wv.x + p1.y * wv.y + p1.z * wv.z + p1.w * wv.w;
            }
            s->z1[r0][l] = fmaxf(s0, 0.f);
            s->z1[r1][l] = fmaxf(s1v, 0.f);
        }
        __syncwarp();

        // S3: z2 = relu(z1 @ Wl2^T + bl2)
        if (l < 20) {
            float bb = s->bl2v[l];
            float s0 = bb, s1v = bb;
            #pragma unroll
            for (int g = 0; g < 5; ++g) {
                float4 wv = *(const float4*)&s->Wl2[l * 20 + 4 * g];
                float4 p0 = *(const float4*)&s->z1[r0][4 * g];
                float4 p1 = *(const float4*)&s->z1[r1][4 * g];
                s0  += p0.x * wv.x + p0.y * wv.y + p0.z * wv.z + p0.w * wv.w;
                s1v += p1.x * wv.x + p1.y * wv.y + p1.z * wv.z + p1.w * wv.w;
            }
            s->z2[r0][l] = fmaxf(s0, 0.f);
            s->z2[r1][l] = fmaxf(s1v, 0.f);
        }
        __syncwarp();

        // S4: z3 = z2 @ Wl3^T + bl3 ; z = zp + dt*z3 ; cond-select into h/c
        {
            float2 b3 = *(const float2*)&s->bl3v[2 * l];
            float z00 = b3.x, z01 = b3.y, z10 = b3.x, z11 = b3.y;
            #pragma unroll
            for (int g = 0; g < 5; ++g) {
                float4 v0 = *(const float4*)&s->z2[r0][4 * g];
                float4 v1 = *(const float4*)&s->z2[r1][4 * g];
                float4 wA = *(const float4*)&s->Wl3Q[(2 * g) * 128 + 4 * l];
                float4 wB = *(const float4*)&s->Wl3Q[(2 * g + 1) * 128 + 4 * l];
                z00 += v0.x * wA.x + v0.y * wA.z + v0.z * wB.x + v0.w * wB.z;
                z01 += v0.x * wA.y + v0.y * wA.w + v0.z * wB.y + v0.w * wB.w;
                z10 += v1.x * wA.x + v1.y * wA.z + v1.z * wB.x + v1.w * wB.z;
                z11 += v1.x * wA.y + v1.y * wA.w + v1.z * wB.y + v1.w * wB.w;
            }
            if (cond0) {
                float2 zz = make_float2(a00 + dt0 * z00, a01 + dt0 * z01);
                if (l < 16) *(float2*)&s->h[r0][2 * l] = zz;
                else        *(float2*)&s->c[r0][2 * l - 32] = zz;
            }
            if (cond1) {
                float2 zz = make_float2(a10 + dt1 * z10, a11 + dt1 * z11);
                if (l < 16) *(float2*)&s->h[r1][2 * l] = zz;
                else        *(float2*)&s->c[r1][2 * l - 32] = zz;
            }
        }
        __syncwarp();

        // S5: gates = bvec + ob@M^T + h_in @ Whh^T   (lane owns cols 4l..4l+3)
        {
            float ac0[4], ac1[4];
            #pragma unroll
            for (int jj = 0; jj < 4; ++jj) {
                ac0[jj] = bv[jj] + obv0.x * M[jj][0] + obv0.y * M[jj][1]
                                 + obv0.z * M[jj][2] + obv0.w * M[jj][3];
                ac1[jj] = bv[jj] + obv1.x * M[jj][0] + obv1.y * M[jj][1]
                                 + obv1.z * M[jj][2] + obv1.w * M[jj][3];
            }
            #pragma unroll
            for (int g = 0; g < 8; ++g) {
                float4 v0 = *(const float4*)&s->h[r0][4 * g];
                float4 v1 = *(const float4*)&s->h[r1][4 * g];
                float4 wA0 = *(const float4*)&s->WhhQ[(2 * g) * 256 + 8 * l];
                float4 wA1 = *(const float4*)&s->WhhQ[(2 * g) * 256 + 8 * l + 4];
                float4 wB0 = *(const float4*)&s->WhhQ[(2 * g + 1) * 256 + 8 * l];
                float4 wB1 = *(const float4*)&s->WhhQ[(2 * g + 1) * 256 + 8 * l + 4];
                ac0[0] += v0.x * wA0.x + v0.y * wA1.x + v0.z * wB0.x + v0.w * wB1.x;
                ac0[1] += v0.x * wA0.y + v0.y * wA1.y + v0.z * wB0.y + v0.w * wB1.y;
                ac0[2] += v0.x * wA0.z + v0.y * wA1.z + v0.z * wB0.z + v0.w * wB1.z;
                ac0[3] += v0.x * wA0.w + v0.y * wA1.w + v0.z * wB0.w + v0.w * wB1.w;
                ac1[0] += v1.x * wA0.x + v1.y * wA1.x + v1.z * wB0.x + v1.w * wB1.x;
                ac1[1] += v1.x * wA0.y + v1.y * wA1.y + v1.z * wB0.y + v1.w * wB1.y;
                ac1[2] += v1.x * wA0.z + v1.y * wA1.z + v1.z * wB0.z + v1.w * wB1.z;
                ac1[3] += v1.x * wA0.w + v1.y * wA1.w + v1.z * wB0.w + v1.w * wB1.w;
            }
            *(float4*)&s->gate[r0][4 * l] = make_float4(ac0[0], ac0[1], ac0[2], ac0[3]);
            *(float4*)&s->gate[r1][4 * l] = make_float4(ac1[0], ac1[1], ac1[2], ac1[3]);
        }
        __syncwarp();

        // S6: LSTM elementwise; update state; write output (unit u = lane)
        {
            const int u = l;
            float gi0 = s->gate[r0][u],      gf0 = s->gate[r0][32 + u];
            float gg0 = s->gate[r0][64 + u], go0 = s->gate[r0][96 + u];
            float gi1 = s->gate[r1][u],      gf1 = s->gate[r1][32 + u];
            float gg1 = s->gate[r1][64 + u], go1 = s->gate[r1][96 + u];
            float ci0 = s->c[r0][u], ci1 = s->c[r1][u];

            float cn0 = sigf(gf0) * ci0 + sigf(gi0) * tanh_f(gg0);
            float cn1 = sigf(gf1) * ci1 + sigf(gi1) * tanh_f(gg1);
            float hn0 = sigf(go0) * tanh_f(cn0);
            float hn1 = sigf(go1) * tanh_f(cn1);

            s->c[r0][u] = cn0; s->h[r0][u] = hn0;
            s->c[r1][u] = cn1; s->h[r1][u] = hn1;

            out[((size_t)g0 * TT + t) * 32 + u] = hn0;
            out[((size_t)g1 * TT + t) * 32 + u] = hn1;
        }
        // no tail barrier: next iteration's S0 __syncwarp orders these
        // h/c/smem writes before any S1 read.
    }
}

extern "C" void kernel_launch(void* const* d_in, const int* in_sizes, int n_in,
                              void* d_out, int out_size)
{
    const float* obs  = (const float*)d_in[0];
    const float* h0   = (const float*)d_in[1];
    const float* c0   = (const float*)d_in[2];
    const float* W1   = (const float*)d_in[3];
    const float* b1   = (const float*)d_in[4];
    const float* W_ih = (const float*)d_in[5];
    const float* W_hh = (const float*)d_in[6];
    const float* b_ih = (const float*)d_in[7];
    const float* b_hh = (const float*)d_in[8];
    const float* W_xi = (const float*)d_in[9];
    const float* b_xi = (const float*)d_in[10];
    const float* Wl1  = (const float*)d_in[11];
    const float* bl1  = (const float*)d_in[12];
    const float* Wl2  = (const float*)d_in[13];
    const float* bl2  = (const float*)d_in[14];
    const float* Wl3  = (const float*)d_in[15];
    const float* bl3  = (const float*)d_in[16];
    float* out = (float*)d_out;

    const int smem_bytes = (int)sizeof(Smem);
    cudaFuncSetAttribute(ppo_rnn_kernel,
                         cudaFuncAttributeMaxDynamicSharedMemorySize, smem_bytes);

    ppo_rnn_kernel<<<NCTA, NTH, smem_bytes>>>(
        obs, h0, c0, W1, b1, W_ih, W_hh, b_ih, b_hh,
        W_xi, b_xi, Wl1, bl1, Wl2, bl2, Wl3, bl3, out);
}